// round 1
// baseline (speedup 1.0000x reference)
#include <cuda_runtime.h>
#include <cstddef>

// Problem constants
#define BQ 8
#define NN 2000
#define TT 64
#define FF 32
#define HH 128
#define NG 512           // 4*H gates
#define KT 160           // H + F combined GEMM depth
#define EE 32000
#define MM 16000         // B*N sequences
#define GHD 128

#define MT 32            // LSTM rows per CTA
#define HSPITCH 168      // padded row (KT + 8)

// ------------------------- device scratch (static, no allocs) -------------
__device__ float g_WT[KT * NG];      // transposed combined weights [k][gate]
__device__ float g_bias[NG];         // bih + bhh
__device__ float g_deg[NN];
__device__ float g_dinv[NN];
__device__ float g_norm[EE];
__device__ float g_h[MM * HH];       // LSTM final hidden
__device__ float g_xw[MM * GHD];     // node_features @ gcn_W
__device__ float g_agg[(size_t)BQ * NN * GHD];

// ------------------------- packed f32x2 helpers ---------------------------
__device__ __forceinline__ unsigned long long pk2(float x, float y) {
    unsigned long long r;
    asm("mov.b64 %0, {%1,%2};" : "=l"(r) : "f"(x), "f"(y));
    return r;
}
__device__ __forceinline__ void upk2(unsigned long long v, float &x, float &y) {
    asm("mov.b64 {%0,%1}, %2;" : "=f"(x), "=f"(y) : "l"(v));
}
__device__ __forceinline__ void fma2(unsigned long long &d,
                                     unsigned long long a,
                                     unsigned long long b) {
    asm("fma.rn.f32x2 %0, %1, %2, %0;" : "+l"(d) : "l"(a), "l"(b));
}

__device__ __forceinline__ float sigmf(float x) {
    return __fdividef(1.f, 1.f + __expf(-x));
}
__device__ __forceinline__ float tanhfast(float x) {
    return __fdividef(2.f, 1.f + __expf(-2.f * x)) - 1.f;
}

// ------------------------- prep: weights + bias ---------------------------
__global__ void k_prep(const float* __restrict__ Wih,
                       const float* __restrict__ Whh,
                       const float* __restrict__ bih,
                       const float* __restrict__ bhh) {
    int idx = blockIdx.x * blockDim.x + threadIdx.x;
    if (idx < KT * NG) {
        int k = idx / NG;
        int n = idx % NG;
        float v = (k < HH) ? Whh[n * HH + k] : Wih[n * FF + (k - HH)];
        g_WT[idx] = v;
    }
    if (idx < NG) g_bias[idx] = bih[idx] + bhh[idx];
}

// ------------------------- graph norm prep --------------------------------
__global__ void k_deg_init() {
    int n = blockIdx.x * blockDim.x + threadIdx.x;
    if (n < NN) g_deg[n] = 1.0f;   // self-loop
}
__global__ void k_deg(const int* __restrict__ ei) {
    int e = blockIdx.x * blockDim.x + threadIdx.x;
    if (e < EE) atomicAdd(&g_deg[ei[EE + e]], 1.0f);  // dst
}
__global__ void k_dinv() {
    int n = blockIdx.x * blockDim.x + threadIdx.x;
    if (n < NN) g_dinv[n] = rsqrtf(g_deg[n]);
}
__global__ void k_norm(const int* __restrict__ ei) {
    int e = blockIdx.x * blockDim.x + threadIdx.x;
    if (e < EE) g_norm[e] = g_dinv[ei[e]] * g_dinv[ei[EE + e]];
}

// ------------------------- fused LSTM --------------------------------------
// 500 CTAs x 256 threads. Each CTA owns MT=32 sequences.
// Thread layout: ty = tid>>6 (m-group of 8), tx = tid&63 (hidden pair u=2*tx).
// Per step: z[32][512] = hs[32][160] @ WT^T (+bias), gates fused in-thread,
// c kept in registers across all 64 steps, h shared via smem.
__global__ __launch_bounds__(256, 2) void k_lstm(const float* __restrict__ x) {
    __shared__ float hs[MT][HSPITCH];

    const int tid = threadIdx.x;
    const int tx = tid & 63;
    const int ty = tid >> 6;
    const int mbase = blockIdx.x * MT;

    // zero the h-region of the A matrix (k < 128)
    for (int idx = tid; idx < MT * HH; idx += 256)
        hs[idx >> 7][idx & 127] = 0.f;

    // bias pairs for this thread's hidden pair, all 4 gates
    unsigned long long bias2[4];
#pragma unroll
    for (int g = 0; g < 4; g++) {
        const float* bp = g_bias + g * HH + 2 * tx;
        bias2[g] = pk2(bp[0], bp[1]);
    }

    float c_st[8][2];
    float hn[8][2];
#pragma unroll
    for (int i = 0; i < 8; i++) {
        c_st[i][0] = 0.f; c_st[i][1] = 0.f;
        hn[i][0] = 0.f;   hn[i][1] = 0.f;
    }

    const float* wbase = g_WT + 2 * tx;

    for (int t = 0; t < TT; t++) {
        __syncthreads();   // all reads of hs from previous GEMM complete

        if (t > 0) {
#pragma unroll
            for (int i = 0; i < 8; i++) {
                float2 hv = make_float2(hn[i][0], hn[i][1]);
                *(float2*)&hs[ty * 8 + i][2 * tx] = hv;
            }
        }
        // stage x_t into k = 128..159
#pragma unroll
        for (int r = 0; r < 4; r++) {
            int idx = tid + r * 256;
            int m = idx >> 5;
            int f = idx & 31;
            hs[m][HH + f] =
                __ldg(&x[(size_t)(mbase + m) * (TT * FF) + t * FF + f]);
        }
        __syncthreads();

        unsigned long long acc[8][4];
#pragma unroll
        for (int i = 0; i < 8; i++) {
#pragma unroll
            for (int g = 0; g < 4; g++) acc[i][g] = bias2[g];
        }

        const float* arow = &hs[ty * 8][0];

#pragma unroll 8
        for (int k = 0; k < KT; k++) {
            const float* wk = wbase + (size_t)k * NG;
            unsigned long long b0 = __ldg((const unsigned long long*)(wk));
            unsigned long long b1 = __ldg((const unsigned long long*)(wk + 128));
            unsigned long long b2 = __ldg((const unsigned long long*)(wk + 256));
            unsigned long long b3 = __ldg((const unsigned long long*)(wk + 384));
#pragma unroll
            for (int i = 0; i < 8; i++) {
                float a = arow[i * HSPITCH + k];
                unsigned long long aa = pk2(a, a);
                fma2(acc[i][0], aa, b0);
                fma2(acc[i][1], aa, b1);
                fma2(acc[i][2], aa, b2);
                fma2(acc[i][3], aa, b3);
            }
        }

        // fused gates (torch order i, f, g, o), c lives in registers
#pragma unroll
        for (int i = 0; i < 8; i++) {
            float zi0, zi1, zf0, zf1, zg0, zg1, zo0, zo1;
            upk2(acc[i][0], zi0, zi1);
            upk2(acc[i][1], zf0, zf1);
            upk2(acc[i][2], zg0, zg1);
            upk2(acc[i][3], zo0, zo1);

            float ig = sigmf(zi0), fg = sigmf(zf0);
            float gg = tanhfast(zg0), og = sigmf(zo0);
            float c = fg * c_st[i][0] + ig * gg;
            c_st[i][0] = c;
            hn[i][0] = og * tanhfast(c);

            ig = sigmf(zi1); fg = sigmf(zf1);
            gg = tanhfast(zg1); og = sigmf(zo1);
            c = fg * c_st[i][1] + ig * gg;
            c_st[i][1] = c;
            hn[i][1] = og * tanhfast(c);
        }
    }

    // final hidden state straight from registers -> gmem
#pragma unroll
    for (int i = 0; i < 8; i++) {
        float2 hv = make_float2(hn[i][0], hn[i][1]);
        *(float2*)&g_h[(size_t)(mbase + ty * 8 + i) * HH + 2 * tx] = hv;
    }
}

// ------------------------- GCN: xw = h @ gcn_W -----------------------------
// 1000 CTAs x 128 threads, 16 rows per CTA, weight broadcast through L1.
__global__ void k_xw(const float* __restrict__ gW) {
    __shared__ float hsm[16][HH];
    const int tid = threadIdx.x;
    const int rowbase = blockIdx.x * 16;

#pragma unroll
    for (int r = 0; r < 16; r++) {
        int idx = tid + r * 128;
        hsm[idx >> 7][idx & 127] = g_h[(size_t)rowbase * HH + idx];
    }
    __syncthreads();

    float acc[16];
#pragma unroll
    for (int r = 0; r < 16; r++) acc[r] = 0.f;

#pragma unroll 4
    for (int k = 0; k < HH; k++) {
        float w = __ldg(&gW[k * GHD + tid]);
#pragma unroll
        for (int r = 0; r < 16; r++) acc[r] += hsm[r][k] * w;
    }
#pragma unroll
    for (int r = 0; r < 16; r++)
        g_xw[(size_t)(rowbase + r) * GHD + tid] = acc[r];
}

// ------------------------- GCN scatter --------------------------------------
__global__ void k_agg_zero() {
    size_t idx = (size_t)blockIdx.x * blockDim.x + threadIdx.x;
    if (idx < (size_t)BQ * NN * GHD) g_agg[idx] = 0.f;
}

// grid.x = E + N messages; 128 threads = feature dim; loop over batches.
__global__ void k_scatter(const int* __restrict__ ei) {
    const int e = blockIdx.x;
    const int c = threadIdx.x;
    int s, d;
    float w;
    if (e < EE) {
        s = ei[e];
        d = ei[EE + e];
        w = g_norm[e];
    } else {
        s = d = e - EE;
        float di = g_dinv[s];
        w = di * di;
    }
#pragma unroll
    for (int b = 0; b < BQ; b++) {
        float v = g_xw[((size_t)b * NN + s) * GHD + c] * w;
        atomicAdd(&g_agg[((size_t)b * NN + d) * GHD + c], v);
    }
}

// ------------------------- MLP head -----------------------------------------
// one CTA per node: silu(agg @ W1 + b1) @ W2 + b2
__global__ void k_mlp(const float* __restrict__ gb,
                      const float* __restrict__ W1,
                      const float* __restrict__ b1,
                      const float* __restrict__ W2,
                      const float* __restrict__ b2,
                      float* __restrict__ out) {
    __shared__ float in_s[GHD];
    __shared__ float red[64];
    const int m = blockIdx.x;
    const int c = threadIdx.x;

    in_s[c] = g_agg[(size_t)m * GHD + c] + __ldg(&gb[c]);
    __syncthreads();

    if (c < 64) {
        float s = __ldg(&b1[c]);
#pragma unroll 8
        for (int k = 0; k < GHD; k++)
            s += in_s[k] * __ldg(&W1[k * 64 + c]);
        float h1 = s * sigmf(s);           // silu
        red[c] = h1 * __ldg(&W2[c]);
    }
    __syncthreads();

    if (c == 0) {
        float s = __ldg(&b2[0]);
#pragma unroll
        for (int j = 0; j < 64; j++) s += red[j];
        out[m] = s;
    }
}

// ------------------------- launch --------------------------------------------
extern "C" void kernel_launch(void* const* d_in, const int* in_sizes, int n_in,
                              void* d_out, int out_size) {
    const float* x   = (const float*)d_in[0];
    const int*   ei  = (const int*)d_in[1];
    const float* Wih = (const float*)d_in[2];
    const float* Whh = (const float*)d_in[3];
    const float* bih = (const float*)d_in[4];
    const float* bhh = (const float*)d_in[5];
    const float* gW  = (const float*)d_in[6];
    const float* gb  = (const float*)d_in[7];
    const float* W1  = (const float*)d_in[8];
    const float* b1  = (const float*)d_in[9];
    const float* W2  = (const float*)d_in[10];
    const float* b2  = (const float*)d_in[11];
    float* out = (float*)d_out;

    k_prep<<<(KT * NG + 255) / 256, 256>>>(Wih, Whh, bih, bhh);
    k_deg_init<<<(NN + 255) / 256, 256>>>();
    k_deg<<<(EE + 255) / 256, 256>>>(ei);
    k_dinv<<<(NN + 255) / 256, 256>>>();
    k_norm<<<(EE + 255) / 256, 256>>>(ei);

    k_lstm<<<MM / MT, 256>>>(x);

    k_xw<<<MM / 16, 128>>>(gW);
    k_agg_zero<<<((size_t)BQ * NN * GHD + 255) / 256, 256>>>();
    k_scatter<<<EE + NN, 128>>>(ei);
    k_mlp<<<MM, 128>>>(gb, W1, b1, W2, b2, out);
}